// round 2
// baseline (speedup 1.0000x reference)
#include <cuda_runtime.h>
#include <cuda_bf16.h>
#include <math.h>

// Problem constants
#define BATCH 32
#define TLEN  256
#define HID   768
#define H     128
#define G3    384   // 3*H
#define NL    9

#define NEG_INF (-1e30f)

// ---------------- scratch (device globals; no allocations allowed) ----------
__device__ float g_xp[2 * TLEN * BATCH * G3];     // [dir][step][b][g]  25.2MB
__device__ float g_hcat[BATCH * TLEN * 2 * H];    // [b][t][256]        8.4MB
__device__ float g_em[BATCH * TLEN * NL];         // emissions
__device__ float g_llh[BATCH];

// ---------------------------------------------------------------------------
// K1: fused embedding gather + input projection GEMM (fp32 SIMT, 64x64x16 tiles)
//     A[i][k] = emb[ids[i]][k],  i = b*256+t   (M=8192, K=768)
//     B cols: n<384 -> Wih_f row n ; n>=384 -> Wih_b row n-384   (N=768)
//     out -> g_xp[dir][step][b][g] + bih
// ---------------------------------------------------------------------------
#define BM 64
#define BN 64
#define BK 16
#define SPAD 68

__global__ __launch_bounds__(256) void gemm_xp_kernel(
    const int* __restrict__ ids, const float* __restrict__ emb,
    const float* __restrict__ Wih_f, const float* __restrict__ Wih_b,
    const float* __restrict__ bih_f, const float* __restrict__ bih_b)
{
    __shared__ __align__(16) float As[BK][SPAD];
    __shared__ __align__(16) float Bs[BK][SPAD];
    __shared__ int ids_s[BM];

    const int m0 = blockIdx.x * BM;
    const int n0 = blockIdx.y * BN;
    const int tid = threadIdx.x;

    if (tid < BM) ids_s[tid] = ids[m0 + tid];
    __syncthreads();

    const int lrow = tid >> 2;        // 0..63
    const int lk   = (tid & 3) * 4;   // 0,4,8,12

    const float* arow = emb + (size_t)ids_s[lrow] * HID;
    const int nrow = n0 + lrow;
    const float* wrow = (nrow < G3) ? (Wih_f + (size_t)nrow * HID)
                                    : (Wih_b + (size_t)(nrow - G3) * HID);

    const int tx = tid & 15;   // N sub
    const int ty = tid >> 4;   // M sub

    float acc[4][4];
#pragma unroll
    for (int i = 0; i < 4; i++)
#pragma unroll
        for (int j = 0; j < 4; j++) acc[i][j] = 0.f;

    for (int k0 = 0; k0 < HID; k0 += BK) {
        float4 av = *(const float4*)(arow + k0 + lk);
        float4 bv = *(const float4*)(wrow + k0 + lk);
        __syncthreads();
        As[lk + 0][lrow] = av.x; As[lk + 1][lrow] = av.y;
        As[lk + 2][lrow] = av.z; As[lk + 3][lrow] = av.w;
        Bs[lk + 0][lrow] = bv.x; Bs[lk + 1][lrow] = bv.y;
        Bs[lk + 2][lrow] = bv.z; Bs[lk + 3][lrow] = bv.w;
        __syncthreads();
#pragma unroll
        for (int kk = 0; kk < BK; kk++) {
            float4 a = *(const float4*)&As[kk][ty * 4];
            float4 b = *(const float4*)&Bs[kk][tx * 4];
            acc[0][0] += a.x * b.x; acc[0][1] += a.x * b.y; acc[0][2] += a.x * b.z; acc[0][3] += a.x * b.w;
            acc[1][0] += a.y * b.x; acc[1][1] += a.y * b.y; acc[1][2] += a.y * b.z; acc[1][3] += a.y * b.w;
            acc[2][0] += a.z * b.x; acc[2][1] += a.z * b.y; acc[2][2] += a.z * b.z; acc[2][3] += a.z * b.w;
            acc[3][0] += a.w * b.x; acc[3][1] += a.w * b.y; acc[3][2] += a.w * b.z; acc[3][3] += a.w * b.w;
        }
    }

#pragma unroll
    for (int ii = 0; ii < 4; ii++) {
        int i = m0 + ty * 4 + ii;
        int b = i >> 8;
        int t = i & 255;
#pragma unroll
        for (int jj = 0; jj < 4; jj++) {
            int n = n0 + tx * 4 + jj;
            int dir = (n >= G3) ? 1 : 0;
            int g = n - dir * G3;
            int step = dir ? (TLEN - 1 - t) : t;
            float bias = dir ? bih_b[g] : bih_f[g];
            g_xp[(((size_t)dir * TLEN + step) * BATCH + b) * G3 + g] = acc[ii][jj] + bias;
        }
    }
}

// ---------------------------------------------------------------------------
// K2: GRU recurrence. One block per (dir,batch). 384 threads, thread g holds
//     Whh row g (128 floats) in registers. 256 sequential steps.
// ---------------------------------------------------------------------------
__global__ __launch_bounds__(384, 1) void gru_kernel(
    const float* __restrict__ Whh_f, const float* __restrict__ bhh_f,
    const float* __restrict__ Whh_b, const float* __restrict__ bhh_b)
{
    const int b   = blockIdx.x & 31;
    const int dir = blockIdx.x >> 5;
    const float* Whh = dir ? Whh_b : Whh_f;
    const float* bhh = dir ? bhh_b : bhh_f;
    const int g = threadIdx.x;

    float w[H];
#pragma unroll
    for (int j = 0; j < H; j++) w[j] = Whh[(size_t)g * H + j];
    const float bias = bhh[g];

    __shared__ __align__(16) float hs[H];
    __shared__ float ghs[G3];
    __shared__ float xs[G3];

    if (g < H) hs[g] = 0.f;

    const float* xp = g_xp + ((size_t)dir * TLEN * BATCH + b) * G3;  // + step*BATCH*G3
    float xnext = xp[g];
    __syncthreads();

    for (int t = 0; t < TLEN; t++) {
        float xt = xnext;
        xs[g] = xt;
        if (t < TLEN - 1) xnext = xp[(size_t)(t + 1) * BATCH * G3 + g];

        float acc0 = bias, acc1 = 0.f;
        const float4* h4 = (const float4*)hs;
#pragma unroll
        for (int j4 = 0; j4 < H / 8; j4++) {
            float4 ha = h4[2 * j4], hb = h4[2 * j4 + 1];
            acc0 += w[8 * j4 + 0] * ha.x; acc1 += w[8 * j4 + 1] * ha.y;
            acc0 += w[8 * j4 + 2] * ha.z; acc1 += w[8 * j4 + 3] * ha.w;
            acc0 += w[8 * j4 + 4] * hb.x; acc1 += w[8 * j4 + 5] * hb.y;
            acc0 += w[8 * j4 + 6] * hb.z; acc1 += w[8 * j4 + 7] * hb.w;
        }
        ghs[g] = acc0 + acc1;
        __syncthreads();

        if (g < H) {
            float r = 1.f / (1.f + __expf(-(xs[g]       + ghs[g])));
            float z = 1.f / (1.f + __expf(-(xs[g + H]   + ghs[g + H])));
            float n = tanhf(xs[g + 2 * H] + r * ghs[g + 2 * H]);
            float hnew = (1.f - z) * n + z * hs[g];
            hs[g] = hnew;
            int tt = dir ? (TLEN - 1 - t) : t;
            g_hcat[((size_t)b * TLEN + tt) * (2 * H) + dir * H + g] = hnew;
        }
        __syncthreads();
    }
}

// ---------------------------------------------------------------------------
// K3: emissions = hcat @ Wlin^T + blin  (M=8192, N=9, K=256). Warp per row.
// ---------------------------------------------------------------------------
__global__ __launch_bounds__(256) void emis_kernel(
    const float* __restrict__ Wlin, const float* __restrict__ blin)
{
    __shared__ float wl[NL][2 * H];
    __shared__ float bl[NL];
    const int tid = threadIdx.x;
    for (int i = tid; i < NL * 2 * H; i += 256) wl[i / (2 * H)][i % (2 * H)] = Wlin[i];
    if (tid < NL) bl[tid] = blin[tid];
    __syncthreads();

    const int warp = tid >> 5, lane = tid & 31;
    const int row = blockIdx.x * 8 + warp;   // b*256 + t
    const float* h = g_hcat + (size_t)row * (2 * H);
    float hv[8];
#pragma unroll
    for (int i = 0; i < 8; i++) hv[i] = h[i * 32 + lane];
#pragma unroll
    for (int l = 0; l < NL; l++) {
        float s = 0.f;
#pragma unroll
        for (int i = 0; i < 8; i++) s += hv[i] * wl[l][i * 32 + lane];
#pragma unroll
        for (int off = 16; off; off >>= 1) s += __shfl_xor_sync(0xffffffffu, s, off);
        if (lane == 0) g_em[(size_t)row * NL + l] = s + bl[l];
    }
}

// ---------------------------------------------------------------------------
// K4: Viterbi (blocks 0..31) + CRF log-likelihood (blocks 32..63).
//     One warp per block; lane j owns label j (lanes 9..31 idle helpers).
// ---------------------------------------------------------------------------
__global__ __launch_bounds__(32) void vitcrf_kernel(
    const float* __restrict__ trans, const float* __restrict__ startv,
    const float* __restrict__ endv, const int* __restrict__ labels,
    float* __restrict__ dout)
{
    const int lane = threadIdx.x;
    const int b = blockIdx.x & 31;
    const bool isV = blockIdx.x < 32;

    float tr[NL];
#pragma unroll
    for (int i = 0; i < NL; i++) tr[i] = (lane < NL) ? trans[i * NL + lane] : 0.f;

    const float* em = g_em + (size_t)b * TLEN * NL;

    if (isV) {
        __shared__ unsigned char bp[TLEN - 1][NL];
        float alpha = (lane < NL) ? startv[lane] + em[lane] : NEG_INF;
        for (int t = 1; t < TLEN; t++) {
            float best = NEG_INF; int bi = 0;
#pragma unroll
            for (int i = 0; i < NL; i++) {
                float ai = __shfl_sync(0xffffffffu, alpha, i);
                float sc = ai + tr[i];
                if (sc > best) { best = sc; bi = i; }
            }
            if (lane < NL) {
                bp[t - 1][lane] = (unsigned char)bi;
                alpha = best + em[t * NL + lane];
            }
        }
        float v = (lane < NL) ? alpha + endv[lane] : NEG_INF;
        int idx = lane;
#pragma unroll
        for (int off = 16; off; off >>= 1) {
            float ov = __shfl_xor_sync(0xffffffffu, v, off);
            int   oi = __shfl_xor_sync(0xffffffffu, idx, off);
            if (ov > v || (ov == v && oi < idx)) { v = ov; idx = oi; }
        }
        __syncwarp();
        if (lane == 0) {
            int y = idx;
            float* outp = dout + b * TLEN;
            outp[TLEN - 1] = (float)y;
            for (int t = TLEN - 2; t >= 0; t--) {
                y = bp[t][y];
                outp[t] = (float)y;
            }
        }
    } else {
        const int* lab = labels + b * TLEN;
        // numerator: strided partial sums
        float s = 0.f;
        for (int t = lane; t < TLEN; t += 32) s += em[t * NL + lab[t]];
        for (int t = lane; t < TLEN - 1; t += 32) s += trans[lab[t] * NL + lab[t + 1]];
#pragma unroll
        for (int off = 16; off; off >>= 1) s += __shfl_xor_sync(0xffffffffu, s, off);
        float num = s + startv[lab[0]] + endv[lab[TLEN - 1]];  // valid in all lanes

        // denominator: forward logsumexp recursion
        float ca = (lane < NL) ? startv[lane] + em[lane] : NEG_INF;
        for (int t = 1; t < TLEN; t++) {
            float vals[NL];
            float best = NEG_INF;
#pragma unroll
            for (int i = 0; i < NL; i++) {
                float ai = __shfl_sync(0xffffffffu, ca, i);
                vals[i] = ai + tr[i];
                best = fmaxf(best, vals[i]);
            }
            float ssum = 0.f;
#pragma unroll
            for (int i = 0; i < NL; i++) ssum += __expf(vals[i] - best);
            ca = (lane < NL) ? (best + __logf(ssum) + em[t * NL + lane]) : NEG_INF;
        }
        float v = (lane < NL) ? ca + endv[lane] : NEG_INF;
        float m = v;
#pragma unroll
        for (int off = 16; off; off >>= 1) m = fmaxf(m, __shfl_xor_sync(0xffffffffu, m, off));
        float ex = (lane < NL) ? __expf(v - m) : 0.f;
#pragma unroll
        for (int off = 16; off; off >>= 1) ex += __shfl_xor_sync(0xffffffffu, ex, off);
        if (lane == 0) g_llh[b] = num - (m + __logf(ex));
    }
}

// ---------------------------------------------------------------------------
// K5: loss = -mean(llh)
// ---------------------------------------------------------------------------
__global__ void loss_kernel(float* __restrict__ dout, int out_size)
{
    float v = g_llh[threadIdx.x];
#pragma unroll
    for (int off = 16; off; off >>= 1) v += __shfl_xor_sync(0xffffffffu, v, off);
    if (threadIdx.x == 0) dout[out_size - 1] = -(v / (float)BATCH);
}

// ---------------------------------------------------------------------------
extern "C" void kernel_launch(void* const* d_in, const int* in_sizes, int n_in,
                              void* d_out, int out_size)
{
    const int*   input_ids = (const int*)d_in[0];
    // d_in[1] = attention_mask (unused, all ones)
    const int*   labels    = (const int*)d_in[2];
    const float* emb       = (const float*)d_in[3];
    const float* Wih_f     = (const float*)d_in[4];
    const float* Whh_f     = (const float*)d_in[5];
    const float* bih_f     = (const float*)d_in[6];
    const float* bhh_f     = (const float*)d_in[7];
    const float* Wih_b     = (const float*)d_in[8];
    const float* Whh_b     = (const float*)d_in[9];
    const float* bih_b     = (const float*)d_in[10];
    const float* bhh_b     = (const float*)d_in[11];
    const float* Wlin      = (const float*)d_in[12];
    const float* blin      = (const float*)d_in[13];
    const float* trans     = (const float*)d_in[14];
    const float* startv    = (const float*)d_in[15];
    const float* endv      = (const float*)d_in[16];
    float* out = (float*)d_out;

    dim3 ggrid(BATCH * TLEN / BM, (2 * G3) / BN);
    gemm_xp_kernel<<<ggrid, 256>>>(input_ids, emb, Wih_f, Wih_b, bih_f, bih_b);
    gru_kernel<<<64, G3>>>(Whh_f, bhh_f, Whh_b, bhh_b);
    emis_kernel<<<BATCH * TLEN / 8, 256>>>(Wlin, blin);
    vitcrf_kernel<<<64, 32>>>(trans, startv, endv, labels, out);
    loss_kernel<<<1, 32>>>(out, out_size);
}

// round 3
// speedup vs baseline: 1.7469x; 1.7469x over previous
#include <cuda_runtime.h>
#include <cuda_bf16.h>
#include <math.h>
#include <stdint.h>

// Problem constants
#define BATCH 32
#define TLEN  256
#define HID   768
#define H     128
#define G3    384   // 3*H
#define NL    9

#define NEG_INF (-1e30f)

// ---------------- scratch (device globals; no allocations allowed) ----------
__device__ float g_xp[2 * TLEN * BATCH * G3];     // [dir][step][b][g]  25.2MB
__device__ float g_hcat[BATCH * TLEN * 2 * H];    // [b][t][256]        8.4MB
__device__ float g_em[BATCH * TLEN * NL];         // emissions
__device__ float g_llh[BATCH];
__device__ __nv_bfloat16 g_wbf[2 * G3 * HID];     // [n][k] bf16 weights (f then b)

// ---------------------------------------------------------------------------
// K0: convert Wih_f / Wih_b -> bf16 panel  [768][768]
// ---------------------------------------------------------------------------
__global__ void conv_w_kernel(const float* __restrict__ Wf, const float* __restrict__ Wb)
{
    int n = blockIdx.x;           // 0..767
    int k = threadIdx.x;          // 0..767
    float v = (n < G3) ? Wf[n * HID + k] : Wb[(n - G3) * HID + k];
    g_wbf[(size_t)n * HID + k] = __float2bfloat16(v);
}

// ---------------------------------------------------------------------------
// K1: embedding gather + input projection GEMM on tensor cores (bf16 HMMA)
//     C[M=8192, N=768] = gather(emb, ids)[M,768] @ Wcat^T, scattered to g_xp.
//     Block 128x128x32, 8 warps (2M x 4N), warp tile 64x32.
// ---------------------------------------------------------------------------
#define BM 128
#define BN 128
#define BKC 32
#define ASZ (BM * BKC)   // elements per buffer

__device__ __forceinline__ void ldsm4(uint32_t* r, uint32_t addr) {
    asm volatile("ldmatrix.sync.aligned.m8n8.x4.shared.b16 {%0,%1,%2,%3}, [%4];\n"
                 : "=r"(r[0]), "=r"(r[1]), "=r"(r[2]), "=r"(r[3]) : "r"(addr));
}
__device__ __forceinline__ void mma16816(float* c, const uint32_t* a, const uint32_t* b) {
    asm volatile(
        "mma.sync.aligned.m16n8k16.row.col.f32.bf16.bf16.f32 "
        "{%0,%1,%2,%3}, {%4,%5,%6,%7}, {%8,%9}, {%0,%1,%2,%3};\n"
        : "+f"(c[0]), "+f"(c[1]), "+f"(c[2]), "+f"(c[3])
        : "r"(a[0]), "r"(a[1]), "r"(a[2]), "r"(a[3]), "r"(b[0]), "r"(b[1]));
}
__device__ __forceinline__ void cpasync16(uint32_t dst, const void* src) {
    asm volatile("cp.async.ca.shared.global [%0], [%1], 16;\n" :: "r"(dst), "l"(src));
}
__device__ __forceinline__ uint4 pack8bf(float4 a, float4 b) {
    __nv_bfloat162 h0 = __float22bfloat162_rn(make_float2(a.x, a.y));
    __nv_bfloat162 h1 = __float22bfloat162_rn(make_float2(a.z, a.w));
    __nv_bfloat162 h2 = __float22bfloat162_rn(make_float2(b.x, b.y));
    __nv_bfloat162 h3 = __float22bfloat162_rn(make_float2(b.z, b.w));
    uint4 u;
    u.x = *(uint32_t*)&h0; u.y = *(uint32_t*)&h1;
    u.z = *(uint32_t*)&h2; u.w = *(uint32_t*)&h3;
    return u;
}

__global__ __launch_bounds__(256) void gemm_xp_tc(
    const int* __restrict__ ids, const float* __restrict__ emb,
    const float* __restrict__ bih_f, const float* __restrict__ bih_b)
{
    __shared__ __align__(16) __nv_bfloat16 As[2 * ASZ];
    __shared__ __align__(16) __nv_bfloat16 Bs[2 * ASZ];
    __shared__ int ids_s[BM];

    const int tid = threadIdx.x;
    const int m0 = blockIdx.x * BM;
    const int n0 = blockIdx.y * BN;

    if (tid < BM) ids_s[tid] = ids[m0 + tid];
    __syncthreads();

    // --- per-thread load slots: s in {tid, tid+256}: row = s>>2, c = s&3 ---
    const int row1 = tid >> 2;          // 0..63
    const int row2 = row1 + 64;         // 64..127
    const int cc   = tid & 3;           // chunk 0..3 (8 elements each)

    const float* aptr1 = emb + (size_t)ids_s[row1] * HID + cc * 8;
    const float* aptr2 = emb + (size_t)ids_s[row2] * HID + cc * 8;
    const __nv_bfloat16* bptr1 = g_wbf + (size_t)(n0 + row1) * HID + cc * 8;
    const __nv_bfloat16* bptr2 = g_wbf + (size_t)(n0 + row2) * HID + cc * 8;

    const uint32_t as_base = (uint32_t)__cvta_generic_to_shared(As);
    const uint32_t bs_base = (uint32_t)__cvta_generic_to_shared(Bs);

    // swizzled element offsets for stores (chunk ^= (row>>1)&3)
    const uint32_t offA1 = (row1 * BKC + ((cc ^ ((row1 >> 1) & 3)) << 3)) * 2;
    const uint32_t offA2 = (row2 * BKC + ((cc ^ ((row2 >> 1) & 3)) << 3)) * 2;

    const int warp = tid >> 5, lane = tid & 31;
    const int wm = warp >> 2, wn = warp & 3;   // 2 x 4
    const int lr = lane & 7, lmi = lane >> 3;

    float acc[4][4][4];
#pragma unroll
    for (int i = 0; i < 4; i++)
#pragma unroll
        for (int j = 0; j < 4; j++)
#pragma unroll
            for (int q = 0; q < 4; q++) acc[i][j][q] = 0.f;

    // ---- prologue: chunk 0 ----
    float4 av10 = *(const float4*)(aptr1);
    float4 av11 = *(const float4*)(aptr1 + 4);
    float4 av20 = *(const float4*)(aptr2);
    float4 av21 = *(const float4*)(aptr2 + 4);
    cpasync16(bs_base + offA1, bptr1);
    cpasync16(bs_base + offA2, bptr2);
    asm volatile("cp.async.commit_group;\n");
    *(uint4*)((char*)As + offA1) = pack8bf(av10, av11);
    *(uint4*)((char*)As + offA2) = pack8bf(av20, av21);
    asm volatile("cp.async.wait_group 0;\n");
    __syncthreads();

    int buf = 0;
    for (int ch = 0; ch < HID / BKC; ch++) {
        const bool has = ch < HID / BKC - 1;
        const int kn = (ch + 1) * BKC;
        if (has) {
            av10 = *(const float4*)(aptr1 + kn);
            av11 = *(const float4*)(aptr1 + kn + 4);
            av20 = *(const float4*)(aptr2 + kn);
            av21 = *(const float4*)(aptr2 + kn + 4);
            const uint32_t bb = (buf ^ 1) * (ASZ * 2);
            cpasync16(bs_base + bb + offA1, bptr1 + kn);
            cpasync16(bs_base + bb + offA2, bptr2 + kn);
            asm volatile("cp.async.commit_group;\n");
        }

        const uint32_t ab = as_base + buf * (ASZ * 2);
        const uint32_t bb = bs_base + buf * (ASZ * 2);
#pragma unroll
        for (int k16 = 0; k16 < 2; k16++) {
            uint32_t afr[4][4];
#pragma unroll
            for (int am = 0; am < 4; am++) {
                int rowA = wm * 64 + am * 16 + lr + ((lmi & 1) << 3);
                int cA = k16 * 2 + (lmi >> 1);
                uint32_t addr = ab + (uint32_t)((rowA * BKC + ((cA ^ ((rowA >> 1) & 3)) << 3)) * 2);
                ldsm4(afr[am], addr);
            }
            uint32_t bfr[4][2];
#pragma unroll
            for (int p = 0; p < 2; p++) {
                int rowB = wn * 32 + p * 16 + lr + ((lmi >> 1) << 3);
                int cB = k16 * 2 + (lmi & 1);
                uint32_t addr = bb + (uint32_t)((rowB * BKC + ((cB ^ ((rowB >> 1) & 3)) << 3)) * 2);
                uint32_t r[4];
                ldsm4(r, addr);
                bfr[2 * p][0] = r[0]; bfr[2 * p][1] = r[1];
                bfr[2 * p + 1][0] = r[2]; bfr[2 * p + 1][1] = r[3];
            }
#pragma unroll
            for (int am = 0; am < 4; am++)
#pragma unroll
                for (int an = 0; an < 4; an++)
                    mma16816(acc[am][an], afr[am], bfr[an]);
        }

        if (has) {
            const uint32_t bboff = (buf ^ 1) * (ASZ * 2);
            *(uint4*)((char*)As + bboff + offA1) = pack8bf(av10, av11);
            *(uint4*)((char*)As + bboff + offA2) = pack8bf(av20, av21);
            asm volatile("cp.async.wait_group 0;\n");
        }
        __syncthreads();
        buf ^= 1;
    }

    // ---- epilogue: scatter to g_xp with bias ----
#pragma unroll
    for (int am = 0; am < 4; am++) {
#pragma unroll
        for (int an = 0; an < 4; an++) {
            int n = n0 + wn * 32 + an * 8 + (lane & 3) * 2;
            int dir = (n >= G3) ? 1 : 0;
            int g = n - dir * G3;
            float b0 = dir ? bih_b[g] : bih_f[g];
            float b1 = dir ? bih_b[g + 1] : bih_f[g + 1];
#pragma unroll
            for (int half = 0; half < 2; half++) {
                int m = m0 + wm * 64 + am * 16 + (lane >> 2) + half * 8;
                int b = m >> 8, t = m & 255;
                int step = dir ? (TLEN - 1 - t) : t;
                float2 v;
                v.x = acc[am][an][2 * half + 0] + b0;
                v.y = acc[am][an][2 * half + 1] + b1;
                *(float2*)&g_xp[(((size_t)dir * TLEN + step) * BATCH + b) * G3 + g] = v;
            }
        }
    }
}

// ---------------------------------------------------------------------------
// K2: GRU recurrence. One block per (dir,batch). 384 threads, thread g holds
//     Whh row g (128 floats) in registers. 256 sequential steps.
// ---------------------------------------------------------------------------
__global__ __launch_bounds__(384, 1) void gru_kernel(
    const float* __restrict__ Whh_f, const float* __restrict__ bhh_f,
    const float* __restrict__ Whh_b, const float* __restrict__ bhh_b)
{
    const int b   = blockIdx.x & 31;
    const int dir = blockIdx.x >> 5;
    const float* Whh = dir ? Whh_b : Whh_f;
    const float* bhh = dir ? bhh_b : bhh_f;
    const int g = threadIdx.x;

    float w[H];
#pragma unroll
    for (int j = 0; j < H; j++) w[j] = Whh[(size_t)g * H + j];
    const float bias = bhh[g];

    __shared__ __align__(16) float hs[H];
    __shared__ float ghs[G3];
    __shared__ float xs[G3];

    if (g < H) hs[g] = 0.f;

    const float* xp = g_xp + ((size_t)dir * TLEN * BATCH + b) * G3;
    float xnext = xp[g];
    __syncthreads();

    for (int t = 0; t < TLEN; t++) {
        float xt = xnext;
        xs[g] = xt;
        if (t < TLEN - 1) xnext = xp[(size_t)(t + 1) * BATCH * G3 + g];

        float acc0 = bias, acc1 = 0.f;
        const float4* h4 = (const float4*)hs;
#pragma unroll
        for (int j4 = 0; j4 < H / 8; j4++) {
            float4 ha = h4[2 * j4], hb = h4[2 * j4 + 1];
            acc0 += w[8 * j4 + 0] * ha.x; acc1 += w[8 * j4 + 1] * ha.y;
            acc0 += w[8 * j4 + 2] * ha.z; acc1 += w[8 * j4 + 3] * ha.w;
            acc0 += w[8 * j4 + 4] * hb.x; acc1 += w[8 * j4 + 5] * hb.y;
            acc0 += w[8 * j4 + 6] * hb.z; acc1 += w[8 * j4 + 7] * hb.w;
        }
        ghs[g] = acc0 + acc1;
        __syncthreads();

        if (g < H) {
            float r = 1.f / (1.f + __expf(-(xs[g]       + ghs[g])));
            float z = 1.f / (1.f + __expf(-(xs[g + H]   + ghs[g + H])));
            float n = tanhf(xs[g + 2 * H] + r * ghs[g + 2 * H]);
            float hnew = (1.f - z) * n + z * hs[g];
            hs[g] = hnew;
            int tt = dir ? (TLEN - 1 - t) : t;
            g_hcat[((size_t)b * TLEN + tt) * (2 * H) + dir * H + g] = hnew;
        }
        __syncthreads();
    }
}

// ---------------------------------------------------------------------------
// K3: emissions = hcat @ Wlin^T + blin  (M=8192, N=9, K=256). Warp per row.
// ---------------------------------------------------------------------------
__global__ __launch_bounds__(256) void emis_kernel(
    const float* __restrict__ Wlin, const float* __restrict__ blin)
{
    __shared__ float wl[NL][2 * H];
    __shared__ float bl[NL];
    const int tid = threadIdx.x;
    for (int i = tid; i < NL * 2 * H; i += 256) wl[i / (2 * H)][i % (2 * H)] = Wlin[i];
    if (tid < NL) bl[tid] = blin[tid];
    __syncthreads();

    const int warp = tid >> 5, lane = tid & 31;
    const int row = blockIdx.x * 8 + warp;   // b*256 + t
    const float* h = g_hcat + (size_t)row * (2 * H);
    float hv[8];
#pragma unroll
    for (int i = 0; i < 8; i++) hv[i] = h[i * 32 + lane];
#pragma unroll
    for (int l = 0; l < NL; l++) {
        float s = 0.f;
#pragma unroll
        for (int i = 0; i < 8; i++) s += hv[i] * wl[l][i * 32 + lane];
#pragma unroll
        for (int off = 16; off; off >>= 1) s += __shfl_xor_sync(0xffffffffu, s, off);
        if (lane == 0) g_em[(size_t)row * NL + l] = s + bl[l];
    }
}

// ---------------------------------------------------------------------------
// K4: Viterbi (blocks 0..31) + CRF log-likelihood (blocks 32..63).
// ---------------------------------------------------------------------------
__global__ __launch_bounds__(32) void vitcrf_kernel(
    const float* __restrict__ trans, const float* __restrict__ startv,
    const float* __restrict__ endv, const int* __restrict__ labels,
    float* __restrict__ dout)
{
    const int lane = threadIdx.x;
    const int b = blockIdx.x & 31;
    const bool isV = blockIdx.x < 32;

    float tr[NL];
#pragma unroll
    for (int i = 0; i < NL; i++) tr[i] = (lane < NL) ? trans[i * NL + lane] : 0.f;

    const float* em = g_em + (size_t)b * TLEN * NL;

    if (isV) {
        __shared__ unsigned char bp[TLEN - 1][NL];
        float alpha = (lane < NL) ? startv[lane] + em[lane] : NEG_INF;
        for (int t = 1; t < TLEN; t++) {
            float best = NEG_INF; int bi = 0;
#pragma unroll
            for (int i = 0; i < NL; i++) {
                float ai = __shfl_sync(0xffffffffu, alpha, i);
                float sc = ai + tr[i];
                if (sc > best) { best = sc; bi = i; }
            }
            if (lane < NL) {
                bp[t - 1][lane] = (unsigned char)bi;
                alpha = best + em[t * NL + lane];
            }
        }
        float v = (lane < NL) ? alpha + endv[lane] : NEG_INF;
        int idx = lane;
#pragma unroll
        for (int off = 16; off; off >>= 1) {
            float ov = __shfl_xor_sync(0xffffffffu, v, off);
            int   oi = __shfl_xor_sync(0xffffffffu, idx, off);
            if (ov > v || (ov == v && oi < idx)) { v = ov; idx = oi; }
        }
        __syncwarp();
        if (lane == 0) {
            int y = idx;
            float* outp = dout + b * TLEN;
            outp[TLEN - 1] = (float)y;
            for (int t = TLEN - 2; t >= 0; t--) {
                y = bp[t][y];
                outp[t] = (float)y;
            }
        }
    } else {
        const int* lab = labels + b * TLEN;
        float s = 0.f;
        for (int t = lane; t < TLEN; t += 32) s += em[t * NL + lab[t]];
        for (int t = lane; t < TLEN - 1; t += 32) s += trans[lab[t] * NL + lab[t + 1]];
#pragma unroll
        for (int off = 16; off; off >>= 1) s += __shfl_xor_sync(0xffffffffu, s, off);
        float num = s + startv[lab[0]] + endv[lab[TLEN - 1]];

        float ca = (lane < NL) ? startv[lane] + em[lane] : NEG_INF;
        for (int t = 1; t < TLEN; t++) {
            float vals[NL];
            float best = NEG_INF;
#pragma unroll
            for (int i = 0; i < NL; i++) {
                float ai = __shfl_sync(0xffffffffu, ca, i);
                vals[i] = ai + tr[i];
                best = fmaxf(best, vals[i]);
            }
            float ssum = 0.f;
#pragma unroll
            for (int i = 0; i < NL; i++) ssum += __expf(vals[i] - best);
            ca = (lane < NL) ? (best + __logf(ssum) + em[t * NL + lane]) : NEG_INF;
        }
        float v = (lane < NL) ? ca + endv[lane] : NEG_INF;
        float m = v;
#pragma unroll
        for (int off = 16; off; off >>= 1) m = fmaxf(m, __shfl_xor_sync(0xffffffffu, m, off));
        float ex = (lane < NL) ? __expf(v - m) : 0.f;
#pragma unroll
        for (int off = 16; off; off >>= 1) ex += __shfl_xor_sync(0xffffffffu, ex, off);
        if (lane == 0) g_llh[b] = num - (m + __logf(ex));
    }
}

// ---------------------------------------------------------------------------
// K5: loss = -mean(llh)
// ---------------------------------------------------------------------------
__global__ void loss_kernel(float* __restrict__ dout, int out_size)
{
    float v = g_llh[threadIdx.x];
#pragma unroll
    for (int off = 16; off; off >>= 1) v += __shfl_xor_sync(0xffffffffu, v, off);
    if (threadIdx.x == 0) dout[out_size - 1] = -(v / (float)BATCH);
}

// ---------------------------------------------------------------------------
extern "C" void kernel_launch(void* const* d_in, const int* in_sizes, int n_in,
                              void* d_out, int out_size)
{
    const int*   input_ids = (const int*)d_in[0];
    const int*   labels    = (const int*)d_in[2];
    const float* emb       = (const float*)d_in[3];
    const float* Wih_f     = (const float*)d_in[4];
    const float* Whh_f     = (const float*)d_in[5];
    const float* bih_f     = (const float*)d_in[6];
    const float* bhh_f     = (const float*)d_in[7];
    const float* Wih_b     = (const float*)d_in[8];
    const float* Whh_b     = (const float*)d_in[9];
    const float* bih_b     = (const float*)d_in[10];
    const float* bhh_b     = (const float*)d_in[11];
    const float* Wlin      = (const float*)d_in[12];
    const float* blin      = (const float*)d_in[13];
    const float* trans     = (const float*)d_in[14];
    const float* startv    = (const float*)d_in[15];
    const float* endv      = (const float*)d_in[16];
    float* out = (float*)d_out;

    conv_w_kernel<<<2 * G3, HID>>>(Wih_f, Wih_b);
    dim3 ggrid((BATCH * TLEN) / BM, (2 * G3) / BN);
    gemm_xp_tc<<<ggrid, 256>>>(input_ids, emb, bih_f, bih_b);
    gru_kernel<<<64, G3>>>(Whh_f, bhh_f, Whh_b, bhh_b);
    emis_kernel<<<BATCH * TLEN / 8, 256>>>(Wlin, blin);
    vitcrf_kernel<<<64, 32>>>(trans, startv, endv, labels, out);
    loss_kernel<<<1, 32>>>(out, out_size);
}

// round 4
// speedup vs baseline: 1.7596x; 1.0073x over previous
#include <cuda_runtime.h>
#include <cuda_bf16.h>
#include <math.h>
#include <stdint.h>

// Problem constants
#define BATCH 32
#define TLEN  256
#define HID   768
#define H     128
#define G3    384   // 3*H
#define NL    9

#define NEG_INF (-1e30f)

// ---------------- scratch (device globals; no allocations allowed) ----------
__device__ float g_xp[2 * TLEN * BATCH * G3];     // [dir][step][b][g]  25.2MB
__device__ float g_hcat[BATCH * TLEN * 2 * H];    // [b][t][256]        8.4MB
__device__ float g_em[BATCH * TLEN * NL];         // emissions
__device__ float g_llh[BATCH];
__device__ __nv_bfloat16 g_wbf[2 * G3 * HID];     // [n][k] bf16 weights (f then b)
__device__ __nv_bfloat16 g_abf[BATCH * TLEN * HID]; // gathered A in bf16 (12.6MB)

// ---------------------------------------------------------------------------
// K0a: convert Wih_f / Wih_b -> bf16 panel  [768][768]
// ---------------------------------------------------------------------------
__global__ void conv_w_kernel(const float* __restrict__ Wf, const float* __restrict__ Wb)
{
    int n = blockIdx.x;           // 0..767
    int k = threadIdx.x;          // 0..767
    float v = (n < G3) ? Wf[n * HID + k] : Wb[(n - G3) * HID + k];
    g_wbf[(size_t)n * HID + k] = __float2bfloat16(v);
}

// ---------------------------------------------------------------------------
// K0b: gather emb rows by input_ids and convert to bf16 -> g_abf [8192][768]
// ---------------------------------------------------------------------------
__global__ __launch_bounds__(192) void conv_a_kernel(
    const int* __restrict__ ids, const float* __restrict__ emb)
{
    int m = blockIdx.x;                  // 0..8191
    int row = __ldg(&ids[m]);
    const float4* src = (const float4*)(emb + (size_t)row * HID);
    float4 v = src[threadIdx.x];
    __nv_bfloat162 lo = __float22bfloat162_rn(make_float2(v.x, v.y));
    __nv_bfloat162 hi = __float22bfloat162_rn(make_float2(v.z, v.w));
    uint2 u;
    u.x = *(uint32_t*)&lo; u.y = *(uint32_t*)&hi;
    *(uint2*)(g_abf + (size_t)m * HID + threadIdx.x * 4) = u;
}

// ---------------------------------------------------------------------------
// K1: input projection GEMM on tensor cores (bf16 HMMA), all-cp.async 3-stage.
//     C[M=8192, N=768] = g_abf[M,768] @ Wcat^T, scattered to g_xp (+bias).
//     Block 128x128x32, 8 warps (2M x 4N), warp tile 64x32.
// ---------------------------------------------------------------------------
#define BM 128
#define BN 128
#define BKC 32
#define ASZ (BM * BKC)   // bf16 elements per stage buffer
#define NK (HID / BKC)   // 24

__device__ __forceinline__ void ldsm4(uint32_t* r, uint32_t addr) {
    asm volatile("ldmatrix.sync.aligned.m8n8.x4.shared.b16 {%0,%1,%2,%3}, [%4];\n"
                 : "=r"(r[0]), "=r"(r[1]), "=r"(r[2]), "=r"(r[3]) : "r"(addr));
}
__device__ __forceinline__ void mma16816(float* c, const uint32_t* a, const uint32_t* b) {
    asm volatile(
        "mma.sync.aligned.m16n8k16.row.col.f32.bf16.bf16.f32 "
        "{%0,%1,%2,%3}, {%4,%5,%6,%7}, {%8,%9}, {%0,%1,%2,%3};\n"
        : "+f"(c[0]), "+f"(c[1]), "+f"(c[2]), "+f"(c[3])
        : "r"(a[0]), "r"(a[1]), "r"(a[2]), "r"(a[3]), "r"(b[0]), "r"(b[1]));
}
__device__ __forceinline__ void cpasync16(uint32_t dst, const void* src) {
    asm volatile("cp.async.ca.shared.global [%0], [%1], 16;\n" :: "r"(dst), "l"(src));
}

__global__ __launch_bounds__(256) void gemm_xp_tc(
    const float* __restrict__ bih_f, const float* __restrict__ bih_b)
{
    __shared__ __align__(16) __nv_bfloat16 As[3 * ASZ];
    __shared__ __align__(16) __nv_bfloat16 Bs[3 * ASZ];

    const int tid = threadIdx.x;
    const int m0 = blockIdx.x * BM;
    const int n0 = blockIdx.y * BN;

    // each thread copies 2x16B chunks for A and 2x16B for B per stage
    const int lrow = tid >> 1;          // 0..127
    const int cpa  = (tid & 1) * 2;     // chunk base: 0 or 2 (8 bf16 per chunk)

    const __nv_bfloat16* aptr = g_abf + (size_t)(m0 + lrow) * HID + cpa * 8;
    const __nv_bfloat16* bptr = g_wbf + (size_t)(n0 + lrow) * HID + cpa * 8;

    const uint32_t as_base = (uint32_t)__cvta_generic_to_shared(As);
    const uint32_t bs_base = (uint32_t)__cvta_generic_to_shared(Bs);

    const int swz = (lrow >> 1) & 3;
    const uint32_t off0 = (uint32_t)((lrow * BKC + ((cpa ^ swz) << 3)) * 2);
    const uint32_t off1 = (uint32_t)((lrow * BKC + (((cpa + 1) ^ swz) << 3)) * 2);

    const int warp = tid >> 5, lane = tid & 31;
    const int wm = warp >> 2, wn = warp & 3;   // 2 x 4
    const int lr = lane & 7, lmi = lane >> 3;

    float acc[4][4][4];
#pragma unroll
    for (int i = 0; i < 4; i++)
#pragma unroll
        for (int j = 0; j < 4; j++)
#pragma unroll
            for (int q = 0; q < 4; q++) acc[i][j][q] = 0.f;

    // prologue: stages 0,1
#pragma unroll
    for (int s = 0; s < 2; s++) {
        uint32_t sb = s * (ASZ * 2);
        cpasync16(as_base + sb + off0, aptr + s * BKC);
        cpasync16(as_base + sb + off1, aptr + s * BKC + 8);
        cpasync16(bs_base + sb + off0, bptr + s * BKC);
        cpasync16(bs_base + sb + off1, bptr + s * BKC + 8);
        asm volatile("cp.async.commit_group;\n");
    }

    int sc = 0;   // compute stage
    int si = 2;   // next issue stage
    for (int ch = 0; ch < NK; ch++) {
        __syncthreads();    // everyone done computing the stage we're about to overwrite
        if (ch + 2 < NK) {
            const uint32_t sb = si * (ASZ * 2);
            const int kk = (ch + 2) * BKC;
            cpasync16(as_base + sb + off0, aptr + kk);
            cpasync16(as_base + sb + off1, aptr + kk + 8);
            cpasync16(bs_base + sb + off0, bptr + kk);
            cpasync16(bs_base + sb + off1, bptr + kk + 8);
            asm volatile("cp.async.commit_group;\n");
            asm volatile("cp.async.wait_group 2;\n");
            si = (si == 2) ? 0 : si + 1;
        } else {
            asm volatile("cp.async.wait_group 0;\n");
        }
        __syncthreads();

        const uint32_t ab = as_base + sc * (ASZ * 2);
        const uint32_t bb = bs_base + sc * (ASZ * 2);
#pragma unroll
        for (int k16 = 0; k16 < 2; k16++) {
            uint32_t afr[4][4];
#pragma unroll
            for (int am = 0; am < 4; am++) {
                int rowA = wm * 64 + am * 16 + lr + ((lmi & 1) << 3);
                int cA = k16 * 2 + (lmi >> 1);
                uint32_t addr = ab + (uint32_t)((rowA * BKC + ((cA ^ ((rowA >> 1) & 3)) << 3)) * 2);
                ldsm4(afr[am], addr);
            }
            uint32_t bfr[4][2];
#pragma unroll
            for (int p = 0; p < 2; p++) {
                int rowB = wn * 32 + p * 16 + lr + ((lmi >> 1) << 3);
                int cB = k16 * 2 + (lmi & 1);
                uint32_t addr = bb + (uint32_t)((rowB * BKC + ((cB ^ ((rowB >> 1) & 3)) << 3)) * 2);
                uint32_t r[4];
                ldsm4(r, addr);
                bfr[2 * p][0] = r[0]; bfr[2 * p][1] = r[1];
                bfr[2 * p + 1][0] = r[2]; bfr[2 * p + 1][1] = r[3];
            }
#pragma unroll
            for (int am = 0; am < 4; am++)
#pragma unroll
                for (int an = 0; an < 4; an++)
                    mma16816(acc[am][an], afr[am], bfr[an]);
        }
        sc = (sc == 2) ? 0 : sc + 1;
    }

    // ---- epilogue: scatter to g_xp with bias ----
#pragma unroll
    for (int am = 0; am < 4; am++) {
#pragma unroll
        for (int an = 0; an < 4; an++) {
            int n = n0 + wn * 32 + an * 8 + (lane & 3) * 2;
            int dir = (n >= G3) ? 1 : 0;
            int g = n - dir * G3;
            float b0 = dir ? bih_b[g] : bih_f[g];
            float b1 = dir ? bih_b[g + 1] : bih_f[g + 1];
#pragma unroll
            for (int half = 0; half < 2; half++) {
                int m = m0 + wm * 64 + am * 16 + (lane >> 2) + half * 8;
                int b = m >> 8, t = m & 255;
                int step = dir ? (TLEN - 1 - t) : t;
                float2 v;
                v.x = acc[am][an][2 * half + 0] + b0;
                v.y = acc[am][an][2 * half + 1] + b1;
                *(float2*)&g_xp[(((size_t)dir * TLEN + step) * BATCH + b) * G3 + g] = v;
            }
        }
    }
}

// ---------------------------------------------------------------------------
// K2: GRU recurrence. One block per (dir,batch). 384 threads, thread g holds
//     Whh row g (128 floats) in registers. 256 sequential steps.
// ---------------------------------------------------------------------------
__global__ __launch_bounds__(384, 1) void gru_kernel(
    const float* __restrict__ Whh_f, const float* __restrict__ bhh_f,
    const float* __restrict__ Whh_b, const float* __restrict__ bhh_b)
{
    const int b   = blockIdx.x & 31;
    const int dir = blockIdx.x >> 5;
    const float* Whh = dir ? Whh_b : Whh_f;
    const float* bhh = dir ? bhh_b : bhh_f;
    const int g = threadIdx.x;

    float w[H];
#pragma unroll
    for (int j = 0; j < H; j++) w[j] = Whh[(size_t)g * H + j];
    const float bias = bhh[g];

    __shared__ __align__(16) float hs[H];
    __shared__ float ghs[G3];
    __shared__ float xs[G3];

    if (g < H) hs[g] = 0.f;

    const float* xp = g_xp + ((size_t)dir * TLEN * BATCH + b) * G3;
    float xnext = xp[g];
    __syncthreads();

    for (int t = 0; t < TLEN; t++) {
        float xt = xnext;
        xs[g] = xt;
        if (t < TLEN - 1) xnext = xp[(size_t)(t + 1) * BATCH * G3 + g];

        float acc0 = bias, acc1 = 0.f;
        const float4* h4 = (const float4*)hs;
#pragma unroll
        for (int j4 = 0; j4 < H / 8; j4++) {
            float4 ha = h4[2 * j4], hb = h4[2 * j4 + 1];
            acc0 += w[8 * j4 + 0] * ha.x; acc1 += w[8 * j4 + 1] * ha.y;
            acc0 += w[8 * j4 + 2] * ha.z; acc1 += w[8 * j4 + 3] * ha.w;
            acc0 += w[8 * j4 + 4] * hb.x; acc1 += w[8 * j4 + 5] * hb.y;
            acc0 += w[8 * j4 + 6] * hb.z; acc1 += w[8 * j4 + 7] * hb.w;
        }
        ghs[g] = acc0 + acc1;
        __syncthreads();

        if (g < H) {
            float r = 1.f / (1.f + __expf(-(xs[g]       + ghs[g])));
            float z = 1.f / (1.f + __expf(-(xs[g + H]   + ghs[g + H])));
            float n = tanhf(xs[g + 2 * H] + r * ghs[g + 2 * H]);
            float hnew = (1.f - z) * n + z * hs[g];
            hs[g] = hnew;
            int tt = dir ? (TLEN - 1 - t) : t;
            g_hcat[((size_t)b * TLEN + tt) * (2 * H) + dir * H + g] = hnew;
        }
        __syncthreads();
    }
}

// ---------------------------------------------------------------------------
// K3: emissions = hcat @ Wlin^T + blin  (M=8192, N=9, K=256). Warp per row.
// ---------------------------------------------------------------------------
__global__ __launch_bounds__(256) void emis_kernel(
    const float* __restrict__ Wlin, const float* __restrict__ blin)
{
    __shared__ float wl[NL][2 * H];
    __shared__ float bl[NL];
    const int tid = threadIdx.x;
    for (int i = tid; i < NL * 2 * H; i += 256) wl[i / (2 * H)][i % (2 * H)] = Wlin[i];
    if (tid < NL) bl[tid] = blin[tid];
    __syncthreads();

    const int warp = tid >> 5, lane = tid & 31;
    const int row = blockIdx.x * 8 + warp;   // b*256 + t
    const float* h = g_hcat + (size_t)row * (2 * H);
    float hv[8];
#pragma unroll
    for (int i = 0; i < 8; i++) hv[i] = h[i * 32 + lane];
#pragma unroll
    for (int l = 0; l < NL; l++) {
        float s = 0.f;
#pragma unroll
        for (int i = 0; i < 8; i++) s += hv[i] * wl[l][i * 32 + lane];
#pragma unroll
        for (int off = 16; off; off >>= 1) s += __shfl_xor_sync(0xffffffffu, s, off);
        if (lane == 0) g_em[(size_t)row * NL + l] = s + bl[l];
    }
}

// ---------------------------------------------------------------------------
// K4: Viterbi + CRF log-likelihood, 8 warps per block (4 Viterbi + 4 CRF
//     interleaved so MUFU/ALU pressure mixes across SMSPs). grid=8.
// ---------------------------------------------------------------------------
__global__ __launch_bounds__(256) void vitcrf_kernel(
    const float* __restrict__ trans, const float* __restrict__ startv,
    const float* __restrict__ endv, const int* __restrict__ labels,
    float* __restrict__ dout)
{
    const int w    = threadIdx.x >> 5;
    const int lane = threadIdx.x & 31;
    const int b    = blockIdx.x * 4 + (w >> 1);   // batch index
    const bool isV = (w & 1) == 0;

    float tr[NL];
#pragma unroll
    for (int i = 0; i < NL; i++) tr[i] = (lane < NL) ? trans[i * NL + lane] : 0.f;

    const float* em = g_em + (size_t)b * TLEN * NL;

    if (isV) {
        __shared__ unsigned char bp[4][TLEN - 1][NL];
        const int vw = w >> 1;
        float alpha = (lane < NL) ? startv[lane] + em[lane] : NEG_INF;
        float ecur = (lane < NL) ? em[NL + lane] : 0.f;
        for (int t = 1; t < TLEN; t++) {
            float enext = (t < TLEN - 1 && lane < NL) ? em[(t + 1) * NL + lane] : 0.f;
            float best = NEG_INF; int bi = 0;
#pragma unroll
            for (int i = 0; i < NL; i++) {
                float ai = __shfl_sync(0xffffffffu, alpha, i);
                float sc = ai + tr[i];
                if (sc > best) { best = sc; bi = i; }
            }
            if (lane < NL) {
                bp[vw][t - 1][lane] = (unsigned char)bi;
                alpha = best + ecur;
            }
            ecur = enext;
        }
        float v = (lane < NL) ? alpha + endv[lane] : NEG_INF;
        int idx = lane;
#pragma unroll
        for (int off = 16; off; off >>= 1) {
            float ov = __shfl_xor_sync(0xffffffffu, v, off);
            int   oi = __shfl_xor_sync(0xffffffffu, idx, off);
            if (ov > v || (ov == v && oi < idx)) { v = ov; idx = oi; }
        }
        __syncwarp();
        if (lane == 0) {
            int y = idx;
            float* outp = dout + b * TLEN;
            outp[TLEN - 1] = (float)y;
            for (int t = TLEN - 2; t >= 0; t--) {
                y = bp[vw][t][y];
                outp[t] = (float)y;
            }
        }
    } else {
        const int* lab = labels + b * TLEN;
        float s = 0.f;
        for (int t = lane; t < TLEN; t += 32) s += em[t * NL + lab[t]];
        for (int t = lane; t < TLEN - 1; t += 32) s += trans[lab[t] * NL + lab[t + 1]];
#pragma unroll
        for (int off = 16; off; off >>= 1) s += __shfl_xor_sync(0xffffffffu, s, off);
        float num = s + startv[lab[0]] + endv[lab[TLEN - 1]];

        float ca = (lane < NL) ? startv[lane] + em[lane] : NEG_INF;
        float ecur = (lane < NL) ? em[NL + lane] : 0.f;
        for (int t = 1; t < TLEN; t++) {
            float enext = (t < TLEN - 1 && lane < NL) ? em[(t + 1) * NL + lane] : 0.f;
            float vals[NL];
#pragma unroll
            for (int i = 0; i < NL; i++) {
                float ai = __shfl_sync(0xffffffffu, ca, i);
                vals[i] = ai + tr[i];
            }
            // pairwise max tree (depth 4)
            float m01 = fmaxf(vals[0], vals[1]), m23 = fmaxf(vals[2], vals[3]);
            float m45 = fmaxf(vals[4], vals[5]), m67 = fmaxf(vals[6], vals[7]);
            float m0123 = fmaxf(m01, m23), m4567 = fmaxf(m45, m67);
            float best = fmaxf(fmaxf(m0123, m4567), vals[8]);
            float ssum = 0.f;
#pragma unroll
            for (int i = 0; i < NL; i++) ssum += __expf(vals[i] - best);
            ca = (lane < NL) ? (best + __logf(ssum) + ecur) : NEG_INF;
            ecur = enext;
        }
        float v = (lane < NL) ? ca + endv[lane] : NEG_INF;
        float m = v;
#pragma unroll
        for (int off = 16; off; off >>= 1) m = fmaxf(m, __shfl_xor_sync(0xffffffffu, m, off));
        float ex = (lane < NL) ? __expf(v - m) : 0.f;
#pragma unroll
        for (int off = 16; off; off >>= 1) ex += __shfl_xor_sync(0xffffffffu, ex, off);
        if (lane == 0) g_llh[b] = num - (m + __logf(ex));
    }
}

// ---------------------------------------------------------------------------
// K5: loss = -mean(llh)
// ---------------------------------------------------------------------------
__global__ void loss_kernel(float* __restrict__ dout, int out_size)
{
    float v = g_llh[threadIdx.x];
#pragma unroll
    for (int off = 16; off; off >>= 1) v += __shfl_xor_sync(0xffffffffu, v, off);
    if (threadIdx.x == 0) dout[out_size - 1] = -(v / (float)BATCH);
}

// ---------------------------------------------------------------------------
extern "C" void kernel_launch(void* const* d_in, const int* in_sizes, int n_in,
                              void* d_out, int out_size)
{
    const int*   input_ids = (const int*)d_in[0];
    const int*   labels    = (const int*)d_in[2];
    const float* emb       = (const float*)d_in[3];
    const float* Wih_f     = (const float*)d_in[4];
    const float* Whh_f     = (const float*)d_in[5];
    const float* bih_f     = (const float*)d_in[6];
    const float* bhh_f     = (const float*)d_in[7];
    const float* Wih_b     = (const float*)d_in[8];
    const float* Whh_b     = (const float*)d_in[9];
    const float* bih_b     = (const float*)d_in[10];
    const float* bhh_b     = (const float*)d_in[11];
    const float* Wlin      = (const float*)d_in[12];
    const float* blin      = (const float*)d_in[13];
    const float* trans     = (const float*)d_in[14];
    const float* startv    = (const float*)d_in[15];
    const float* endv      = (const float*)d_in[16];
    float* out = (float*)d_out;

    conv_w_kernel<<<2 * G3, HID>>>(Wih_f, Wih_b);
    conv_a_kernel<<<BATCH * TLEN, 192>>>(input_ids, emb);
    dim3 ggrid((BATCH * TLEN) / BM, (2 * G3) / BN);
    gemm_xp_tc<<<ggrid, 256>>>(bih_f, bih_b);
    gru_kernel<<<64, G3>>>(Whh_f, bhh_f, Whh_b, bhh_b);
    emis_kernel<<<BATCH * TLEN / 8, 256>>>(Wlin, blin);
    vitcrf_kernel<<<8, 256>>>(trans, startv, endv, labels, out);
    loss_kernel<<<1, 32>>>(out, out_size);
}

// round 6
// speedup vs baseline: 1.7953x; 1.0203x over previous
#include <cuda_runtime.h>
#include <cuda_bf16.h>
#include <math.h>
#include <stdint.h>

// Problem constants
#define BATCH 32
#define TLEN  256
#define HID   768
#define H     128
#define G3    384   // 3*H
#define NL    9

#define NEG_INF (-1e30f)

// ---------------- scratch (device globals; no allocations allowed) ----------
__device__ float g_xp[2 * TLEN * BATCH * G3];     // [dir][step][b][g]  25.2MB
__device__ float g_hcat[BATCH * TLEN * 2 * H];    // [b][t][256]        8.4MB
__device__ float g_em[BATCH * TLEN * NL];         // emissions
__device__ float g_llh[BATCH];
__device__ __nv_bfloat16 g_wbf[2 * G3 * HID];     // [n][k] bf16 weights (f then b)
__device__ __nv_bfloat16 g_abf[BATCH * TLEN * HID]; // gathered A in bf16 (12.6MB)

// ---------------------------------------------------------------------------
// K0a: convert Wih_f / Wih_b -> bf16 panel  [768][768]
// ---------------------------------------------------------------------------
__global__ void conv_w_kernel(const float* __restrict__ Wf, const float* __restrict__ Wb)
{
    int n = blockIdx.x;           // 0..767
    int k = threadIdx.x;          // 0..767
    float v = (n < G3) ? Wf[n * HID + k] : Wb[(n - G3) * HID + k];
    g_wbf[(size_t)n * HID + k] = __float2bfloat16(v);
}

// ---------------------------------------------------------------------------
// K0b: gather emb rows by input_ids and convert to bf16 -> g_abf [8192][768]
// ---------------------------------------------------------------------------
__global__ __launch_bounds__(192) void conv_a_kernel(
    const int* __restrict__ ids, const float* __restrict__ emb)
{
    int m = blockIdx.x;                  // 0..8191
    int row = __ldg(&ids[m]);
    const float4* src = (const float4*)(emb + (size_t)row * HID);
    float4 v = src[threadIdx.x];
    __nv_bfloat162 lo = __float22bfloat162_rn(make_float2(v.x, v.y));
    __nv_bfloat162 hi = __float22bfloat162_rn(make_float2(v.z, v.w));
    uint2 u;
    u.x = *(uint32_t*)&lo; u.y = *(uint32_t*)&hi;
    *(uint2*)(g_abf + (size_t)m * HID + threadIdx.x * 4) = u;
}

// ---------------------------------------------------------------------------
// K1: input projection GEMM on tensor cores (bf16 HMMA), all-cp.async 3-stage.
// ---------------------------------------------------------------------------
#define BM 128
#define BN 128
#define BKC 32
#define ASZ (BM * BKC)   // bf16 elements per stage buffer
#define NK (HID / BKC)   // 24

__device__ __forceinline__ void ldsm4(uint32_t* r, uint32_t addr) {
    asm volatile("ldmatrix.sync.aligned.m8n8.x4.shared.b16 {%0,%1,%2,%3}, [%4];\n"
                 : "=r"(r[0]), "=r"(r[1]), "=r"(r[2]), "=r"(r[3]) : "r"(addr));
}
__device__ __forceinline__ void mma16816(float* c, const uint32_t* a, const uint32_t* b) {
    asm volatile(
        "mma.sync.aligned.m16n8k16.row.col.f32.bf16.bf16.f32 "
        "{%0,%1,%2,%3}, {%4,%5,%6,%7}, {%8,%9}, {%0,%1,%2,%3};\n"
        : "+f"(c[0]), "+f"(c[1]), "+f"(c[2]), "+f"(c[3])
        : "r"(a[0]), "r"(a[1]), "r"(a[2]), "r"(a[3]), "r"(b[0]), "r"(b[1]));
}
__device__ __forceinline__ void cpasync16(uint32_t dst, const void* src) {
    asm volatile("cp.async.ca.shared.global [%0], [%1], 16;\n" :: "r"(dst), "l"(src));
}

__global__ __launch_bounds__(256) void gemm_xp_tc(
    const float* __restrict__ bih_f, const float* __restrict__ bih_b)
{
    __shared__ __align__(16) __nv_bfloat16 As[3 * ASZ];
    __shared__ __align__(16) __nv_bfloat16 Bs[3 * ASZ];

    const int tid = threadIdx.x;
    const int m0 = blockIdx.x * BM;
    const int n0 = blockIdx.y * BN;

    const int lrow = tid >> 1;          // 0..127
    const int cpa  = (tid & 1) * 2;     // chunk base: 0 or 2 (8 bf16 per chunk)

    const __nv_bfloat16* aptr = g_abf + (size_t)(m0 + lrow) * HID + cpa * 8;
    const __nv_bfloat16* bptr = g_wbf + (size_t)(n0 + lrow) * HID + cpa * 8;

    const uint32_t as_base = (uint32_t)__cvta_generic_to_shared(As);
    const uint32_t bs_base = (uint32_t)__cvta_generic_to_shared(Bs);

    const int swz = (lrow >> 1) & 3;
    const uint32_t off0 = (uint32_t)((lrow * BKC + ((cpa ^ swz) << 3)) * 2);
    const uint32_t off1 = (uint32_t)((lrow * BKC + (((cpa + 1) ^ swz) << 3)) * 2);

    const int warp = tid >> 5, lane = tid & 31;
    const int wm = warp >> 2, wn = warp & 3;   // 2 x 4
    const int lr = lane & 7, lmi = lane >> 3;

    float acc[4][4][4];
#pragma unroll
    for (int i = 0; i < 4; i++)
#pragma unroll
        for (int j = 0; j < 4; j++)
#pragma unroll
            for (int q = 0; q < 4; q++) acc[i][j][q] = 0.f;

#pragma unroll
    for (int s = 0; s < 2; s++) {
        uint32_t sb = s * (ASZ * 2);
        cpasync16(as_base + sb + off0, aptr + s * BKC);
        cpasync16(as_base + sb + off1, aptr + s * BKC + 8);
        cpasync16(bs_base + sb + off0, bptr + s * BKC);
        cpasync16(bs_base + sb + off1, bptr + s * BKC + 8);
        asm volatile("cp.async.commit_group;\n");
    }

    int sc = 0;
    int si = 2;
    for (int ch = 0; ch < NK; ch++) {
        __syncthreads();
        if (ch + 2 < NK) {
            const uint32_t sb = si * (ASZ * 2);
            const int kk = (ch + 2) * BKC;
            cpasync16(as_base + sb + off0, aptr + kk);
            cpasync16(as_base + sb + off1, aptr + kk + 8);
            cpasync16(bs_base + sb + off0, bptr + kk);
            cpasync16(bs_base + sb + off1, bptr + kk + 8);
            asm volatile("cp.async.commit_group;\n");
            asm volatile("cp.async.wait_group 2;\n");
            si = (si == 2) ? 0 : si + 1;
        } else {
            asm volatile("cp.async.wait_group 0;\n");
        }
        __syncthreads();

        const uint32_t ab = as_base + sc * (ASZ * 2);
        const uint32_t bb = bs_base + sc * (ASZ * 2);
#pragma unroll
        for (int k16 = 0; k16 < 2; k16++) {
            uint32_t afr[4][4];
#pragma unroll
            for (int am = 0; am < 4; am++) {
                int rowA = wm * 64 + am * 16 + lr + ((lmi & 1) << 3);
                int cA = k16 * 2 + (lmi >> 1);
                uint32_t addr = ab + (uint32_t)((rowA * BKC + ((cA ^ ((rowA >> 1) & 3)) << 3)) * 2);
                ldsm4(afr[am], addr);
            }
            uint32_t bfr[4][2];
#pragma unroll
            for (int p = 0; p < 2; p++) {
                int rowB = wn * 32 + p * 16 + lr + ((lmi >> 1) << 3);
                int cB = k16 * 2 + (lmi & 1);
                uint32_t addr = bb + (uint32_t)((rowB * BKC + ((cB ^ ((rowB >> 1) & 3)) << 3)) * 2);
                uint32_t r[4];
                ldsm4(r, addr);
                bfr[2 * p][0] = r[0]; bfr[2 * p][1] = r[1];
                bfr[2 * p + 1][0] = r[2]; bfr[2 * p + 1][1] = r[3];
            }
#pragma unroll
            for (int am = 0; am < 4; am++)
#pragma unroll
                for (int an = 0; an < 4; an++)
                    mma16816(acc[am][an], afr[am], bfr[an]);
        }
        sc = (sc == 2) ? 0 : sc + 1;
    }

#pragma unroll
    for (int am = 0; am < 4; am++) {
#pragma unroll
        for (int an = 0; an < 4; an++) {
            int n = n0 + wn * 32 + an * 8 + (lane & 3) * 2;
            int dir = (n >= G3) ? 1 : 0;
            int g = n - dir * G3;
            float b0 = dir ? bih_b[g] : bih_f[g];
            float b1 = dir ? bih_b[g + 1] : bih_f[g + 1];
#pragma unroll
            for (int half = 0; half < 2; half++) {
                int m = m0 + wm * 64 + am * 16 + (lane >> 2) + half * 8;
                int b = m >> 8, t = m & 255;
                int step = dir ? (TLEN - 1 - t) : t;
                float2 v;
                v.x = acc[am][an][2 * half + 0] + b0;
                v.y = acc[am][an][2 * half + 1] + b1;
                *(float2*)&g_xp[(((size_t)dir * TLEN + step) * BATCH + b) * G3 + g] = v;
            }
        }
    }
}

// ---------------------------------------------------------------------------
// K2: GRU recurrence with packed fp32x2 FMA (fma.rn.f32x2 — exact fp32,
//     2 FMAs per issue). One block per (dir,batch). Thread g holds Whh row g
//     as 64 packed f32x2 pairs; h read from smem as v2.u64 pairs.
// ---------------------------------------------------------------------------
__device__ __forceinline__ void fma2(uint64_t& d, uint64_t a, uint64_t b) {
    asm volatile("fma.rn.f32x2 %0, %1, %2, %0;" : "+l"(d) : "l"(a), "l"(b));
}

__global__ __launch_bounds__(384, 1) void gru_kernel(
    const float* __restrict__ Whh_f, const float* __restrict__ bhh_f,
    const float* __restrict__ Whh_b, const float* __restrict__ bhh_b)
{
    const int b   = blockIdx.x & 31;
    const int dir = blockIdx.x >> 5;
    const float* Whh = dir ? Whh_b : Whh_f;
    const float* bhh = dir ? bhh_b : bhh_f;
    const int g = threadIdx.x;

    // pack Whh row g into 64 f32x2 register pairs
    uint64_t w2[H / 2];
#pragma unroll
    for (int j = 0; j < H / 2; j++) {
        float2 v = *(const float2*)&Whh[(size_t)g * H + 2 * j];
        uint64_t u;
        asm("mov.b64 %0, {%1,%2};" : "=l"(u)
            : "r"(__float_as_uint(v.x)), "r"(__float_as_uint(v.y)));
        w2[j] = u;
    }
    const float bias = bhh[g];

    __shared__ __align__(16) float hs[H];
    __shared__ float ghs[G3];
    __shared__ float xs[G3];

    if (g < H) hs[g] = 0.f;

    const uint32_t hs_addr = (uint32_t)__cvta_generic_to_shared(hs);

    const float* xp = g_xp + ((size_t)dir * TLEN * BATCH + b) * G3;
    float xnext = xp[g];
    __syncthreads();

    for (int t = 0; t < TLEN; t++) {
        float xt = xnext;
        xs[g] = xt;
        if (t < TLEN - 1) xnext = xp[(size_t)(t + 1) * BATCH * G3 + g];

        // matvec: gh[g] = sum_j Whh[g][j] * h[j]  via 32 packed FMA2
        uint64_t acc_a, acc_b;
        {
            uint64_t p0, p1;
            asm volatile("ld.shared.v2.u64 {%0,%1}, [%2];"
                         : "=l"(p0), "=l"(p1) : "r"(hs_addr));
            uint64_t za = 0, zb = 0;
            asm volatile("mul.rn.f32x2 %0, %1, %2;" : "=l"(za) : "l"(w2[0]), "l"(p0));
            asm volatile("mul.rn.f32x2 %0, %1, %2;" : "=l"(zb) : "l"(w2[1]), "l"(p1));
            acc_a = za; acc_b = zb;
        }
#pragma unroll
        for (int j = 1; j < H / 4; j++) {
            uint64_t p0, p1;
            asm volatile("ld.shared.v2.u64 {%0,%1}, [%2];"
                         : "=l"(p0), "=l"(p1) : "r"(hs_addr + 16 * j));
            fma2(acc_a, w2[2 * j], p0);
            fma2(acc_b, w2[2 * j + 1], p1);
        }
        // reduce the two packed accumulators
        uint32_t alo, ahi, blo, bhi;
        asm("mov.b64 {%0,%1}, %2;" : "=r"(alo), "=r"(ahi) : "l"(acc_a));
        asm("mov.b64 {%0,%1}, %2;" : "=r"(blo), "=r"(bhi) : "l"(acc_b));
        float gh = bias + ((__uint_as_float(alo) + __uint_as_float(ahi)) +
                           (__uint_as_float(blo) + __uint_as_float(bhi)));
        ghs[g] = gh;
        __syncthreads();

        if (g < H) {
            float r = 1.f / (1.f + __expf(-(xs[g]       + ghs[g])));
            float z = 1.f / (1.f + __expf(-(xs[g + H]   + ghs[g + H])));
            float n = tanhf(xs[g + 2 * H] + r * ghs[g + 2 * H]);
            float hnew = (1.f - z) * n + z * hs[g];
            hs[g] = hnew;
            int tt = dir ? (TLEN - 1 - t) : t;
            g_hcat[((size_t)b * TLEN + tt) * (2 * H) + dir * H + g] = hnew;
        }
        __syncthreads();
    }
}

// ---------------------------------------------------------------------------
// K3: emissions = hcat @ Wlin^T + blin  (M=8192, N=9, K=256). Warp per row.
// ---------------------------------------------------------------------------
__global__ __launch_bounds__(256) void emis_kernel(
    const float* __restrict__ Wlin, const float* __restrict__ blin)
{
    __shared__ float wl[NL][2 * H];
    __shared__ float bl[NL];
    const int tid = threadIdx.x;
    for (int i = tid; i < NL * 2 * H; i += 256) wl[i / (2 * H)][i % (2 * H)] = Wlin[i];
    if (tid < NL) bl[tid] = blin[tid];
    __syncthreads();

    const int warp = tid >> 5, lane = tid & 31;
    const int row = blockIdx.x * 8 + warp;   // b*256 + t
    const float* h = g_hcat + (size_t)row * (2 * H);
    float hv[8];
#pragma unroll
    for (int i = 0; i < 8; i++) hv[i] = h[i * 32 + lane];
#pragma unroll
    for (int l = 0; l < NL; l++) {
        float s = 0.f;
#pragma unroll
        for (int i = 0; i < 8; i++) s += hv[i] * wl[l][i * 32 + lane];
#pragma unroll
        for (int off = 16; off; off >>= 1) s += __shfl_xor_sync(0xffffffffu, s, off);
        if (lane == 0) g_em[(size_t)row * NL + l] = s + bl[l];
    }
}

// ---------------------------------------------------------------------------
// K4: Viterbi + CRF log-likelihood, 8 warps per block (4 Viterbi + 4 CRF).
// ---------------------------------------------------------------------------
__global__ __launch_bounds__(256) void vitcrf_kernel(
    const float* __restrict__ trans, const float* __restrict__ startv,
    const float* __restrict__ endv, const int* __restrict__ labels,
    float* __restrict__ dout)
{
    const int w    = threadIdx.x >> 5;
    const int lane = threadIdx.x & 31;
    const int b    = blockIdx.x * 4 + (w >> 1);   // batch index
    const bool isV = (w & 1) == 0;

    float tr[NL];
#pragma unroll
    for (int i = 0; i < NL; i++) tr[i] = (lane < NL) ? trans[i * NL + lane] : 0.f;

    const float* em = g_em + (size_t)b * TLEN * NL;

    if (isV) {
        __shared__ unsigned char bp[4][TLEN - 1][NL];
        const int vw = w >> 1;
        float alpha = (lane < NL) ? startv[lane] + em[lane] : NEG_INF;
        float ecur = (lane < NL) ? em[NL + lane] : 0.f;
        for (int t = 1; t < TLEN; t++) {
            float enext = (t < TLEN - 1 && lane < NL) ? em[(t + 1) * NL + lane] : 0.f;
            float best = NEG_INF; int bi = 0;
#pragma unroll
            for (int i = 0; i < NL; i++) {
                float ai = __shfl_sync(0xffffffffu, alpha, i);
                float sc = ai + tr[i];
                if (sc > best) { best = sc; bi = i; }
            }
            if (lane < NL) {
                bp[vw][t - 1][lane] = (unsigned char)bi;
                alpha = best + ecur;
            }
            ecur = enext;
        }
        float v = (lane < NL) ? alpha + endv[lane] : NEG_INF;
        int idx = lane;
#pragma unroll
        for (int off = 16; off; off >>= 1) {
            float ov = __shfl_xor_sync(0xffffffffu, v, off);
            int   oi = __shfl_xor_sync(0xffffffffu, idx, off);
            if (ov > v || (ov == v && oi < idx)) { v = ov; idx = oi; }
        }
        __syncwarp();
        if (lane == 0) {
            int y = idx;
            float* outp = dout + b * TLEN;
            outp[TLEN - 1] = (float)y;
            for (int t = TLEN - 2; t >= 0; t--) {
                y = bp[vw][t][y];
                outp[t] = (float)y;
            }
        }
    } else {
        const int* lab = labels + b * TLEN;
        float s = 0.f;
        for (int t = lane; t < TLEN; t += 32) s += em[t * NL + lab[t]];
        for (int t = lane; t < TLEN - 1; t += 32) s += trans[lab[t] * NL + lab[t + 1]];
#pragma unroll
        for (int off = 16; off; off >>= 1) s += __shfl_xor_sync(0xffffffffu, s, off);
        float num = s + startv[lab[0]] + endv[lab[TLEN - 1]];

        float ca = (lane < NL) ? startv[lane] + em[lane] : NEG_INF;
        float ecur = (lane < NL) ? em[NL + lane] : 0.f;
        for (int t = 1; t < TLEN; t++) {
            float enext = (t < TLEN - 1 && lane < NL) ? em[(t + 1) * NL + lane] : 0.f;
            float vals[NL];
#pragma unroll
            for (int i = 0; i < NL; i++) {
                float ai = __shfl_sync(0xffffffffu, ca, i);
                vals[i] = ai + tr[i];
            }
            float m01 = fmaxf(vals[0], vals[1]), m23 = fmaxf(vals[2], vals[3]);
            float m45 = fmaxf(vals[4], vals[5]), m67 = fmaxf(vals[6], vals[7]);
            float m0123 = fmaxf(m01, m23), m4567 = fmaxf(m45, m67);
            float best = fmaxf(fmaxf(m0123, m4567), vals[8]);
            float ssum = 0.f;
#pragma unroll
            for (int i = 0; i < NL; i++) ssum += __expf(vals[i] - best);
            ca = (lane < NL) ? (best + __logf(ssum) + ecur) : NEG_INF;
            ecur = enext;
        }
        float v = (lane < NL) ? ca + endv[lane] : NEG_INF;
        float m = v;
#pragma unroll
        for (int off = 16; off; off >>= 1) m = fmaxf(m, __shfl_xor_sync(0xffffffffu, m, off));
        float ex = (lane < NL) ? __expf(v - m) : 0.f;
#pragma unroll
        for (int off = 16; off; off >>= 1) ex += __shfl_xor_sync(0xffffffffu, ex, off);
        if (lane == 0) g_llh[b] = num - (m + __logf(ex));
    }
}

// ---------------------------------------------------------------------------
// K5: loss = -mean(llh)
// ---------------------------------------------------------------------------
__global__ void loss_kernel(float* __restrict__ dout, int out_size)
{
    float v = g_llh[threadIdx.x];
#pragma unroll
    for (int off = 16; off; off >>= 1) v += __shfl_xor_sync(0xffffffffu, v, off);
    if (threadIdx.x == 0) dout[out_size - 1] = -(v / (float)BATCH);
}

// ---------------------------------------------------------------------------
extern "C" void kernel_launch(void* const* d_in, const int* in_sizes, int n_in,
                              void* d_out, int out_size)
{
    const int*   input_ids = (const int*)d_in[0];
    const int*   labels    = (const int*)d_in[2];
    const float* emb       = (const float*)d_in[3];
    const float* Wih_f     = (const float*)d_in[4];
    const float* Whh_f     = (const float*)d_in[5];
    const float* bih_f     = (const float*)d_in[6];
    const float* bhh_f     = (const float*)d_in[7];
    const float* Wih_b     = (const float*)d_in[8];
    const float* Whh_b     = (const float*)d_in[9];
    const float* bih_b     = (const float*)d_in[10];
    const float* bhh_b     = (const float*)d_in[11];
    const float* Wlin      = (const float*)d_in[12];
    const float* blin      = (const float*)d_in[13];
    const float* trans     = (const float*)d_in[14];
    const float* startv    = (const float*)d_in[15];
    const float* endv      = (const float*)d_in[16];
    float* out = (float*)d_out;

    conv_w_kernel<<<2 * G3, HID>>>(Wih_f, Wih_b);
    conv_a_kernel<<<BATCH * TLEN, 192>>>(input_ids, emb);
    dim3 ggrid((BATCH * TLEN) / BM, (2 * G3) / BN);
    gemm_xp_tc<<<ggrid, 256>>>(bih_f, bih_b);
    gru_kernel<<<64, G3>>>(Whh_f, bhh_f, Whh_b, bhh_b);
    emis_kernel<<<BATCH * TLEN / 8, 256>>>(Wlin, blin);
    vitcrf_kernel<<<8, 256>>>(trans, startv, endv, labels, out);
    loss_kernel<<<1, 32>>>(out, out_size);
}

// round 9
// speedup vs baseline: 2.1112x; 1.1759x over previous
#include <cuda_runtime.h>
#include <cuda_bf16.h>
#include <math.h>
#include <stdint.h>

// Problem constants
#define BATCH 32
#define TLEN  256
#define HID   768
#define H     128
#define G3    384   // 3*H
#define NL    9

#define NEG_INF (-1e30f)

// ---------------- scratch (device globals; no allocations allowed) ----------
__device__ float g_xp[2 * TLEN * BATCH * G3];     // [dir][step][b][g]  25.2MB
__device__ float g_hcat[BATCH * TLEN * 2 * H];    // [b][t][256]        8.4MB
__device__ float g_em[BATCH * TLEN * NL];         // emissions
__device__ float g_llh[BATCH];
__device__ __nv_bfloat16 g_wbf[2 * G3 * HID];     // [n][k] bf16 weights (f then b)
__device__ __nv_bfloat16 g_abf[BATCH * TLEN * HID]; // gathered A in bf16 (12.6MB)

// ---------------------------------------------------------------------------
// K0a: convert Wih_f / Wih_b -> bf16 panel  [768][768]
// ---------------------------------------------------------------------------
__global__ void conv_w_kernel(const float* __restrict__ Wf, const float* __restrict__ Wb)
{
    int n = blockIdx.x;           // 0..767
    int k = threadIdx.x;          // 0..767
    float v = (n < G3) ? Wf[n * HID + k] : Wb[(n - G3) * HID + k];
    g_wbf[(size_t)n * HID + k] = __float2bfloat16(v);
}

// ---------------------------------------------------------------------------
// K0b: gather emb rows by input_ids and convert to bf16 -> g_abf [8192][768]
// ---------------------------------------------------------------------------
__global__ __launch_bounds__(192) void conv_a_kernel(
    const int* __restrict__ ids, const float* __restrict__ emb)
{
    int m = blockIdx.x;                  // 0..8191
    int row = __ldg(&ids[m]);
    const float4* src = (const float4*)(emb + (size_t)row * HID);
    float4 v = src[threadIdx.x];
    __nv_bfloat162 lo = __float22bfloat162_rn(make_float2(v.x, v.y));
    __nv_bfloat162 hi = __float22bfloat162_rn(make_float2(v.z, v.w));
    uint2 u;
    u.x = *(uint32_t*)&lo; u.y = *(uint32_t*)&hi;
    *(uint2*)(g_abf + (size_t)m * HID + threadIdx.x * 4) = u;
}

// ---------------------------------------------------------------------------
// K1: input projection GEMM on tensor cores (bf16 HMMA), all-cp.async 3-stage.
// ---------------------------------------------------------------------------
#define BM 128
#define BN 128
#define BKC 32
#define ASZ (BM * BKC)   // bf16 elements per stage buffer
#define NK (HID / BKC)   // 24

__device__ __forceinline__ void ldsm4(uint32_t* r, uint32_t addr) {
    asm volatile("ldmatrix.sync.aligned.m8n8.x4.shared.b16 {%0,%1,%2,%3}, [%4];\n"
                 : "=r"(r[0]), "=r"(r[1]), "=r"(r[2]), "=r"(r[3]) : "r"(addr));
}
__device__ __forceinline__ void mma16816(float* c, const uint32_t* a, const uint32_t* b) {
    asm volatile(
        "mma.sync.aligned.m16n8k16.row.col.f32.bf16.bf16.f32 "
        "{%0,%1,%2,%3}, {%4,%5,%6,%7}, {%8,%9}, {%0,%1,%2,%3};\n"
        : "+f"(c[0]), "+f"(c[1]), "+f"(c[2]), "+f"(c[3])
        : "r"(a[0]), "r"(a[1]), "r"(a[2]), "r"(a[3]), "r"(b[0]), "r"(b[1]));
}
__device__ __forceinline__ void cpasync16(uint32_t dst, const void* src) {
    asm volatile("cp.async.ca.shared.global [%0], [%1], 16;\n" :: "r"(dst), "l"(src));
}

__global__ __launch_bounds__(256) void gemm_xp_tc(
    const float* __restrict__ bih_f, const float* __restrict__ bih_b)
{
    __shared__ __align__(16) __nv_bfloat16 As[3 * ASZ];
    __shared__ __align__(16) __nv_bfloat16 Bs[3 * ASZ];

    const int tid = threadIdx.x;
    const int m0 = blockIdx.x * BM;
    const int n0 = blockIdx.y * BN;

    const int lrow = tid >> 1;          // 0..127
    const int cpa  = (tid & 1) * 2;     // chunk base: 0 or 2 (8 bf16 per chunk)

    const __nv_bfloat16* aptr = g_abf + (size_t)(m0 + lrow) * HID + cpa * 8;
    const __nv_bfloat16* bptr = g_wbf + (size_t)(n0 + lrow) * HID + cpa * 8;

    const uint32_t as_base = (uint32_t)__cvta_generic_to_shared(As);
    const uint32_t bs_base = (uint32_t)__cvta_generic_to_shared(Bs);

    const int swz = (lrow >> 1) & 3;
    const uint32_t off0 = (uint32_t)((lrow * BKC + ((cpa ^ swz) << 3)) * 2);
    const uint32_t off1 = (uint32_t)((lrow * BKC + (((cpa + 1) ^ swz) << 3)) * 2);

    const int warp = tid >> 5, lane = tid & 31;
    const int wm = warp >> 2, wn = warp & 3;   // 2 x 4
    const int lr = lane & 7, lmi = lane >> 3;

    float acc[4][4][4];
#pragma unroll
    for (int i = 0; i < 4; i++)
#pragma unroll
        for (int j = 0; j < 4; j++)
#pragma unroll
            for (int q = 0; q < 4; q++) acc[i][j][q] = 0.f;

#pragma unroll
    for (int s = 0; s < 2; s++) {
        uint32_t sb = s * (ASZ * 2);
        cpasync16(as_base + sb + off0, aptr + s * BKC);
        cpasync16(as_base + sb + off1, aptr + s * BKC + 8);
        cpasync16(bs_base + sb + off0, bptr + s * BKC);
        cpasync16(bs_base + sb + off1, bptr + s * BKC + 8);
        asm volatile("cp.async.commit_group;\n");
    }

    int sc = 0;
    int si = 2;
    for (int ch = 0; ch < NK; ch++) {
        __syncthreads();
        if (ch + 2 < NK) {
            const uint32_t sb = si * (ASZ * 2);
            const int kk = (ch + 2) * BKC;
            cpasync16(as_base + sb + off0, aptr + kk);
            cpasync16(as_base + sb + off1, aptr + kk + 8);
            cpasync16(bs_base + sb + off0, bptr + kk);
            cpasync16(bs_base + sb + off1, bptr + kk + 8);
            asm volatile("cp.async.commit_group;\n");
            asm volatile("cp.async.wait_group 2;\n");
            si = (si == 2) ? 0 : si + 1;
        } else {
            asm volatile("cp.async.wait_group 0;\n");
        }
        __syncthreads();

        const uint32_t ab = as_base + sc * (ASZ * 2);
        const uint32_t bb = bs_base + sc * (ASZ * 2);
#pragma unroll
        for (int k16 = 0; k16 < 2; k16++) {
            uint32_t afr[4][4];
#pragma unroll
            for (int am = 0; am < 4; am++) {
                int rowA = wm * 64 + am * 16 + lr + ((lmi & 1) << 3);
                int cA = k16 * 2 + (lmi >> 1);
                uint32_t addr = ab + (uint32_t)((rowA * BKC + ((cA ^ ((rowA >> 1) & 3)) << 3)) * 2);
                ldsm4(afr[am], addr);
            }
            uint32_t bfr[4][2];
#pragma unroll
            for (int p = 0; p < 2; p++) {
                int rowB = wn * 32 + p * 16 + lr + ((lmi >> 1) << 3);
                int cB = k16 * 2 + (lmi & 1);
                uint32_t addr = bb + (uint32_t)((rowB * BKC + ((cB ^ ((rowB >> 1) & 3)) << 3)) * 2);
                uint32_t r[4];
                ldsm4(r, addr);
                bfr[2 * p][0] = r[0]; bfr[2 * p][1] = r[1];
                bfr[2 * p + 1][0] = r[2]; bfr[2 * p + 1][1] = r[3];
            }
#pragma unroll
            for (int am = 0; am < 4; am++)
#pragma unroll
                for (int an = 0; an < 4; an++)
                    mma16816(acc[am][an], afr[am], bfr[an]);
        }
        sc = (sc == 2) ? 0 : sc + 1;
    }

#pragma unroll
    for (int am = 0; am < 4; am++) {
#pragma unroll
        for (int an = 0; an < 4; an++) {
            int n = n0 + wn * 32 + an * 8 + (lane & 3) * 2;
            int dir = (n >= G3) ? 1 : 0;
            int g = n - dir * G3;
            float b0 = dir ? bih_b[g] : bih_f[g];
            float b1 = dir ? bih_b[g + 1] : bih_f[g + 1];
#pragma unroll
            for (int half = 0; half < 2; half++) {
                int m = m0 + wm * 64 + am * 16 + (lane >> 2) + half * 8;
                int b = m >> 8, t = m & 255;
                int step = dir ? (TLEN - 1 - t) : t;
                float2 v;
                v.x = acc[am][an][2 * half + 0] + b0;
                v.y = acc[am][an][2 * half + 1] + b1;
                *(float2*)&g_xp[(((size_t)dir * TLEN + step) * BATCH + b) * G3 + g] = v;
            }
        }
    }
}

// ---------------------------------------------------------------------------
// K2: GRU recurrence. fp32x2 packed FMA (NON-volatile so ptxas can pipeline
//     the shared loads), MUFU tanh.approx activations.
// ---------------------------------------------------------------------------
__device__ __forceinline__ uint64_t packf2(float lo, float hi) {
    uint64_t u;
    asm("mov.b64 %0, {%1,%2};" : "=l"(u)
        : "r"(__float_as_uint(lo)), "r"(__float_as_uint(hi)));
    return u;
}
__device__ __forceinline__ void fma2(uint64_t& d, uint64_t a, uint64_t b) {
    asm("fma.rn.f32x2 %0, %1, %2, %0;" : "+l"(d) : "l"(a), "l"(b));
}
__device__ __forceinline__ float tanh_fast(float x) {
    float y;
    asm("tanh.approx.f32 %0, %1;" : "=f"(y) : "f"(x));
    return y;
}
__device__ __forceinline__ float sigmoid_fast(float x) {
    // sigmoid(x) = 0.5*tanh(0.5x) + 0.5  (single MUFU)
    return fmaf(0.5f, tanh_fast(0.5f * x), 0.5f);
}

__global__ __launch_bounds__(384, 1) void gru_kernel(
    const float* __restrict__ Whh_f, const float* __restrict__ bhh_f,
    const float* __restrict__ Whh_b, const float* __restrict__ bhh_b)
{
    const int b   = blockIdx.x & 31;
    const int dir = blockIdx.x >> 5;
    const float* Whh = dir ? Whh_b : Whh_f;
    const float* bhh = dir ? bhh_b : bhh_f;
    const int g = threadIdx.x;

    // pack Whh row g into 64 f32x2 register pairs
    uint64_t w2[H / 2];
#pragma unroll
    for (int j = 0; j < H / 2; j++) {
        float2 v = *(const float2*)&Whh[(size_t)g * H + 2 * j];
        w2[j] = packf2(v.x, v.y);
    }
    const float bias = bhh[g];

    __shared__ __align__(16) float hs[H];
    __shared__ float ghs[G3];
    __shared__ float xs[G3];

    if (g < H) hs[g] = 0.f;

    const float* xp = g_xp + ((size_t)dir * TLEN * BATCH + b) * G3;
    float xnext = xp[g];
    __syncthreads();

    for (int t = 0; t < TLEN; t++) {
        xs[g] = xnext;
        if (t < TLEN - 1) xnext = xp[(size_t)(t + 1) * BATCH * G3 + g];

        // matvec: gh[g] = bias + sum_j Whh[g][j]*h[j] via 32 packed FMA2.
        // Plain C++ float4 loads -> ptxas batches/hoists LDS (restores MLP).
        const float4* h4 = (const float4*)hs;
        uint64_t acc_a = packf2(bias, 0.f);
        uint64_t acc_b = packf2(0.f, 0.f);
#pragma unroll
        for (int j = 0; j < H / 8; j++) {
            float4 ha = h4[2 * j];
            float4 hb = h4[2 * j + 1];
            fma2(acc_a, w2[4 * j + 0], packf2(ha.x, ha.y));
            fma2(acc_b, w2[4 * j + 1], packf2(ha.z, ha.w));
            fma2(acc_a, w2[4 * j + 2], packf2(hb.x, hb.y));
            fma2(acc_b, w2[4 * j + 3], packf2(hb.z, hb.w));
        }
        uint32_t alo, ahi, blo, bhi;
        asm("mov.b64 {%0,%1}, %2;" : "=r"(alo), "=r"(ahi) : "l"(acc_a));
        asm("mov.b64 {%0,%1}, %2;" : "=r"(blo), "=r"(bhi) : "l"(acc_b));
        ghs[g] = (__uint_as_float(alo) + __uint_as_float(ahi)) +
                 (__uint_as_float(blo) + __uint_as_float(bhi));
        __syncthreads();

        if (g < H) {
            float r = sigmoid_fast(xs[g] + ghs[g]);
            float z = sigmoid_fast(xs[g + H] + ghs[g + H]);
            float n = tanh_fast(xs[g + 2 * H] + r * ghs[g + 2 * H]);
            float hnew = (1.f - z) * n + z * hs[g];
            hs[g] = hnew;
            int tt = dir ? (TLEN - 1 - t) : t;
            g_hcat[((size_t)b * TLEN + tt) * (2 * H) + dir * H + g] = hnew;
        }
        __syncthreads();
    }
}

// ---------------------------------------------------------------------------
// K3: emissions = hcat @ Wlin^T + blin  (M=8192, N=9, K=256). Warp per row.
// ---------------------------------------------------------------------------
__global__ __launch_bounds__(256) void emis_kernel(
    const float* __restrict__ Wlin, const float* __restrict__ blin)
{
    __shared__ float wl[NL][2 * H];
    __shared__ float bl[NL];
    const int tid = threadIdx.x;
    for (int i = tid; i < NL * 2 * H; i += 256) wl[i / (2 * H)][i % (2 * H)] = Wlin[i];
    if (tid < NL) bl[tid] = blin[tid];
    __syncthreads();

    const int warp = tid >> 5, lane = tid & 31;
    const int row = blockIdx.x * 8 + warp;   // b*256 + t
    const float* h = g_hcat + (size_t)row * (2 * H);
    float hv[8];
#pragma unroll
    for (int i = 0; i < 8; i++) hv[i] = h[i * 32 + lane];
#pragma unroll
    for (int l = 0; l < NL; l++) {
        float s = 0.f;
#pragma unroll
        for (int i = 0; i < 8; i++) s += hv[i] * wl[l][i * 32 + lane];
#pragma unroll
        for (int off = 16; off; off >>= 1) s += __shfl_xor_sync(0xffffffffu, s, off);
        if (lane == 0) g_em[(size_t)row * NL + l] = s + bl[l];
    }
}

// ---------------------------------------------------------------------------
// K4: Viterbi + CRF log-likelihood, 8 warps per block (4 Viterbi + 4 CRF).
// ---------------------------------------------------------------------------
__global__ __launch_bounds__(256) void vitcrf_kernel(
    const float* __restrict__ trans, const float* __restrict__ startv,
    const float* __restrict__ endv, const int* __restrict__ labels,
    float* __restrict__ dout)
{
    const int w    = threadIdx.x >> 5;
    const int lane = threadIdx.x & 31;
    const int b    = blockIdx.x * 4 + (w >> 1);   // batch index
    const bool isV = (w & 1) == 0;

    float tr[NL];
#pragma unroll
    for (int i = 0; i < NL; i++) tr[i] = (lane < NL) ? trans[i * NL + lane] : 0.f;

    const float* em = g_em + (size_t)b * TLEN * NL;

    if (isV) {
        __shared__ unsigned char bp[4][TLEN - 1][NL];
        const int vw = w >> 1;
        float alpha = (lane < NL) ? startv[lane] + em[lane] : NEG_INF;
        float ecur = (lane < NL) ? em[NL + lane] : 0.f;
        for (int t = 1; t < TLEN; t++) {
            float enext = (t < TLEN - 1 && lane < NL) ? em[(t + 1) * NL + lane] : 0.f;
            float best = NEG_INF; int bi = 0;
#pragma unroll
            for (int i = 0; i < NL; i++) {
                float ai = __shfl_sync(0xffffffffu, alpha, i);
                float sc = ai + tr[i];
                if (sc > best) { best = sc; bi = i; }
            }
            if (lane < NL) {
                bp[vw][t - 1][lane] = (unsigned char)bi;
                alpha = best + ecur;
            }
            ecur = enext;
        }
        float v = (lane < NL) ? alpha + endv[lane] : NEG_INF;
        int idx = lane;
#pragma unroll
        for (int off = 16; off; off >>= 1) {
            float ov = __shfl_xor_sync(0xffffffffu, v, off);
            int   oi = __shfl_xor_sync(0xffffffffu, idx, off);
            if (ov > v || (ov == v && oi < idx)) { v = ov; idx = oi; }
        }
        __syncwarp();
        if (lane == 0) {
            int y = idx;
            float* outp = dout + b * TLEN;
            outp[TLEN - 1] = (float)y;
            for (int t = TLEN - 2; t >= 0; t--) {
                y = bp[vw][t][y];
                outp[t] = (float)y;
            }
        }
    } else {
        const int* lab = labels + b * TLEN;
        float s = 0.f;
        for (int t = lane; t < TLEN; t += 32) s += em[t * NL + lab[t]];
        for (int t = lane; t < TLEN - 1; t += 32) s += trans[lab[t] * NL + lab[t + 1]];
#pragma unroll
        for (int off = 16; off; off >>= 1) s += __shfl_xor_sync(0xffffffffu, s, off);
        float num = s + startv[lab[0]] + endv[lab[TLEN - 1]];

        float ca = (lane < NL) ? startv[lane] + em[lane] : NEG_INF;
        float ecur = (lane < NL) ? em[NL + lane] : 0.f;
        for (int t = 1; t < TLEN; t++) {
            float enext = (t < TLEN - 1 && lane < NL) ? em[(t + 1) * NL + lane] : 0.f;
            float vals[NL];
#pragma unroll
            for (int i = 0; i < NL; i++) {
                float ai = __shfl_sync(0xffffffffu, ca, i);
                vals[i] = ai + tr[i];
            }
            float m01 = fmaxf(vals[0], vals[1]), m23 = fmaxf(vals[2], vals[3]);
            float m45 = fmaxf(vals[4], vals[5]), m67 = fmaxf(vals[6], vals[7]);
            float m0123 = fmaxf(m01, m23), m4567 = fmaxf(m45, m67);
            float best = fmaxf(fmaxf(m0123, m4567), vals[8]);
            float ssum = 0.f;
#pragma unroll
            for (int i = 0; i < NL; i++) ssum += __expf(vals[i] - best);
            ca = (lane < NL) ? (best + __logf(ssum) + ecur) : NEG_INF;
            ecur = enext;
        }
        float v = (lane < NL) ? ca + endv[lane] : NEG_INF;
        float m = v;
#pragma unroll
        for (int off = 16; off; off >>= 1) m = fmaxf(m, __shfl_xor_sync(0xffffffffu, m, off));
        float ex = (lane < NL) ? __expf(v - m) : 0.f;
#pragma unroll
        for (int off = 16; off; off >>= 1) ex += __shfl_xor_sync(0xffffffffu, ex, off);
        if (lane == 0) g_llh[b] = num - (m + __logf(ex));
    }
}

// ---------------------------------------------------------------------------
// K5: loss = -mean(llh)
// ---------------------------------------------------------------------------
__global__ void loss_kernel(float* __restrict__ dout, int out_size)
{
    float v = g_llh[threadIdx.x];
#pragma unroll
    for (int off = 16; off; off >>= 1) v += __shfl_xor_sync(0xffffffffu, v, off);
    if (threadIdx.x == 0) dout[out_size - 1] = -(v / (float)BATCH);
}

// ---------------------------------------------------------------------------
extern "C" void kernel_launch(void* const* d_in, const int* in_sizes, int n_in,
                              void* d_out, int out_size)
{
    const int*   input_ids = (const int*)d_in[0];
    const int*   labels    = (const int*)d_in[2];
    const float* emb       = (const float*)d_in[3];
    const float* Wih_f     = (const float*)d_in[4];
    const float* Whh_f     = (const float*)d_in[5];
    const float* bih_f     = (const float*)d_in[6];
    const float* bhh_f     = (const float*)d_in[7];
    const float* Wih_b     = (const float*)d_in[8];
    const float* Whh_b     = (const float*)d_in[9];
    const float* bih_b     = (const float*)d_in[10];
    const float* bhh_b     = (const float*)d_in[11];
    const float* Wlin      = (const float*)d_in[12];
    const float* blin      = (const float*)d_in[13];
    const float* trans     = (const float*)d_in[14];
    const float* startv    = (const float*)d_in[15];
    const float* endv      = (const float*)d_in[16];
    float* out = (float*)d_out;

    conv_w_kernel<<<2 * G3, HID>>>(Wih_f, Wih_b);
    conv_a_kernel<<<BATCH * TLEN, 192>>>(input_ids, emb);
    dim3 ggrid((BATCH * TLEN) / BM, (2 * G3) / BN);
    gemm_xp_tc<<<ggrid, 256>>>(bih_f, bih_b);
    gru_kernel<<<64, G3>>>(Whh_f, bhh_f, Whh_b, bhh_b);
    emis_kernel<<<BATCH * TLEN / 8, 256>>>(Wlin, blin);
    vitcrf_kernel<<<8, 256>>>(trans, startv, endv, labels, out);
    loss_kernel<<<1, 32>>>(out, out_size);
}